// round 3
// baseline (speedup 1.0000x reference)
#include <cuda_runtime.h>
#include <cstdint>

#define HID    256
#define TDIM   1024
#define NSTEP  1023
#define IN_DIM 35

// output layout: coeff [256][1023][5] | mean [256][1023][5][32] | var [256][1023][5]
#define MEANBASE 1309440
#define VARBASE  43211520

// ---------------- device scratch (allocation-free) ----------------
__device__ float g_H[(size_t)NSTEP * 256 * 256];   // h history, [t][k=256][b=256]
__device__ float g_W1t[256 * 112];                 // k-major, M padded 100->112
__device__ float g_W2t[112 * 112];
__device__ float g_W3t[112 * 176];                 // M padded 170->176
__device__ float g_b1p[112];
__device__ float g_b2p[112];
__device__ float g_b3p[176];
__device__ unsigned g_bar[8];

// ---------------- prep: reset barriers, transpose/pad MDN weights ----------------
__global__ void prep_kernel(const float* __restrict__ W1, const float* __restrict__ b1,
                            const float* __restrict__ W2, const float* __restrict__ b2,
                            const float* __restrict__ W3, const float* __restrict__ b3)
{
    int id = blockIdx.x * blockDim.x + threadIdx.x;
    int stride = gridDim.x * blockDim.x;
    if (id < 8) g_bar[id] = 0u;
    for (int i = id; i < 256 * 112; i += stride) {
        int k = i / 112, m = i - k * 112;
        g_W1t[i] = (m < 100) ? W1[m * 256 + k] : 0.f;
    }
    for (int i = id; i < 112 * 112; i += stride) {
        int k = i / 112, m = i - k * 112;
        g_W2t[i] = (k < 100 && m < 100) ? W2[m * 100 + k] : 0.f;
    }
    for (int i = id; i < 112 * 176; i += stride) {
        int k = i / 176, m = i - k * 176;
        g_W3t[i] = (k < 100 && m < 170) ? W3[m * 100 + k] : 0.f;
    }
    for (int i = id; i < 112; i += stride) {
        g_b1p[i] = (i < 100) ? b1[i] : 0.f;
        g_b2p[i] = (i < 100) ? b2[i] : 0.f;
    }
    for (int i = id; i < 176; i += stride) g_b3p[i] = (i < 170) ? b3[i] : 0.f;
}

__device__ __forceinline__ float sigf(float v)     { return 1.f / (1.f + __expf(-v)); }
__device__ __forceinline__ float tanhfast(float v) { return 1.f - 2.f / (__expf(2.f * v) + 1.f); }

// ---------------- persistent LSTM ----------------
// grid 128: jg = blockIdx>>3 (16 hid-tiles of 16), bg = blockIdx&7 (8 batch-tiles of 32)
#define LSTM_SMEM_BYTES ((256*64 + 36*64 + 64 + 256*32 + 36*32 + 64*36 + 16*32) * 4)

__global__ void __launch_bounds__(128, 1)
lstm_kernel(const float* __restrict__ x, const float* __restrict__ W_ih,
            const float* __restrict__ W_hh, const float* __restrict__ b_ih,
            const float* __restrict__ b_hh)
{
    extern __shared__ float sm[];
    float* Whh  = sm;               // [k=256][m=64] k-major
    float* Wih  = Whh + 256 * 64;   // [c=36][m=64]  (row 35 = zero pad)
    float* bias = Wih + 36 * 64;    // [64]
    float* hT   = bias + 64;        // [k=256][n=32]
    float* xT   = hT + 256 * 32;    // [c=36][n=32]
    float* Gs   = xT + 36 * 32;     // [m=64][ld=36]
    float* cS   = Gs + 64 * 36;     // [16][32] cell state

    const int tid = threadIdx.x;
    const int bg  = blockIdx.x & 7;
    const int jg  = blockIdx.x >> 3;

    // one-time weight staging
    for (int i = tid; i < 64 * 64; i += 128) {
        int m  = i >> 6;
        int kc = (i & 63) << 2;
        int j  = ((m >> 4) << 8) + (jg << 4) + (m & 15);   // gate*256 + jg*16 + jh
        float4 w = *reinterpret_cast<const float4*>(&W_hh[j * 256 + kc]);
        Whh[(kc + 0) * 64 + m] = w.x;
        Whh[(kc + 1) * 64 + m] = w.y;
        Whh[(kc + 2) * 64 + m] = w.z;
        Whh[(kc + 3) * 64 + m] = w.w;
    }
    for (int i = tid; i < 36 * 64; i += 128) {
        int c = i >> 6, m = i & 63;
        int j = ((m >> 4) << 8) + (jg << 4) + (m & 15);
        Wih[c * 64 + m] = (c < 35) ? W_ih[j * 35 + c] : 0.f;
    }
    if (tid < 64) {
        int j = ((tid >> 4) << 8) + (jg << 4) + (tid & 15);
        bias[tid] = b_ih[j] + b_hh[j];
    }
    for (int i = tid; i < 512; i += 128) cS[i] = 0.f;
    if (tid < 32) xT[35 * 32 + tid] = 0.f;   // pad row, persists
    __syncthreads();

    const int tm  = tid & 15;   // GEMM: rows 4tm..4tm+3
    const int tb  = tid >> 4;   // GEMM: cols 4tb..4tb+3
    const int cjh = tid >> 3;   // combine: jh
    const int cnb = tid & 7;    // combine: batch quad

    for (int t = 0; t < NSTEP; ++t) {
        // stage x [35][32]
        for (int i = tid; i < 32 * 35; i += 128) {
            int n = i / 35, c = i - n * 35;
            int b = (bg << 5) + n;
            xT[c * 32 + n] = x[((size_t)b * TDIM + t) * IN_DIM + c];
        }
        // stage h(t-1) [256][32]
        if (t > 0) {
            const float* hp = g_H + (size_t)(t - 1) * 65536 + (bg << 5);
            for (int i = tid; i < 2048; i += 128) {
                int k = i >> 3, nb = i & 7;
                float4 v = *reinterpret_cast<const float4*>(hp + (size_t)k * 256 + nb * 4);
                *reinterpret_cast<float4*>(&hT[k * 32 + nb * 4]) = v;
            }
        }
        __syncthreads();

        // GEMM 64x32, K = 36 + 256
        float acc[4][4];
#pragma unroll
        for (int i = 0; i < 4; ++i)
#pragma unroll
            for (int j = 0; j < 4; ++j) acc[i][j] = 0.f;

#pragma unroll 4
        for (int c = 0; c < 36; ++c) {
            float4 a  = *reinterpret_cast<const float4*>(&Wih[c * 64 + (tm << 2)]);
            float4 b4 = *reinterpret_cast<const float4*>(&xT[c * 32 + (tb << 2)]);
            float av[4] = {a.x, a.y, a.z, a.w};
            float bv[4] = {b4.x, b4.y, b4.z, b4.w};
#pragma unroll
            for (int i = 0; i < 4; ++i)
#pragma unroll
                for (int j = 0; j < 4; ++j) acc[i][j] = fmaf(av[i], bv[j], acc[i][j]);
        }
        if (t > 0) {
#pragma unroll 8
            for (int k = 0; k < 256; ++k) {
                float4 a  = *reinterpret_cast<const float4*>(&Whh[k * 64 + (tm << 2)]);
                float4 b4 = *reinterpret_cast<const float4*>(&hT[k * 32 + (tb << 2)]);
                float av[4] = {a.x, a.y, a.z, a.w};
                float bv[4] = {b4.x, b4.y, b4.z, b4.w};
#pragma unroll
                for (int i = 0; i < 4; ++i)
#pragma unroll
                    for (int j = 0; j < 4; ++j) acc[i][j] = fmaf(av[i], bv[j], acc[i][j]);
            }
        }
#pragma unroll
        for (int i = 0; i < 4; ++i)
            *reinterpret_cast<float4*>(&Gs[((tm << 2) + i) * 36 + (tb << 2)]) =
                make_float4(acc[i][0], acc[i][1], acc[i][2], acc[i][3]);
        __syncthreads();

        // gate combine; c stays in smem, h -> global (coalesced)
        {
            float4 gi = *reinterpret_cast<const float4*>(&Gs[(cjh)      * 36 + (cnb << 2)]);
            float4 gf = *reinterpret_cast<const float4*>(&Gs[(16 + cjh) * 36 + (cnb << 2)]);
            float4 gg = *reinterpret_cast<const float4*>(&Gs[(32 + cjh) * 36 + (cnb << 2)]);
            float4 go = *reinterpret_cast<const float4*>(&Gs[(48 + cjh) * 36 + (cnb << 2)]);
            float bi = bias[cjh], bf = bias[16 + cjh], bgv = bias[32 + cjh], bo = bias[48 + cjh];
            float4 co = *reinterpret_cast<const float4*>(&cS[cjh * 32 + (cnb << 2)]);
            float4 cn, hn;
#define COMB(L) { float iv = sigf(gi.L + bi); float fv = sigf(gf.L + bf);          \
                  float gv = tanhfast(gg.L + bgv); float ov = sigf(go.L + bo);     \
                  float cv = fv * co.L + iv * gv; cn.L = cv; hn.L = ov * tanhfast(cv); }
            COMB(x) COMB(y) COMB(z) COMB(w)
#undef COMB
            *reinterpret_cast<float4*>(&cS[cjh * 32 + (cnb << 2)]) = cn;
            float* hout = g_H + (size_t)t * 65536 + (size_t)(((jg << 4) + cjh) << 8)
                          + (bg << 5) + (cnb << 2);
            *reinterpret_cast<float4*>(hout) = hn;
        }
        __threadfence();
        __syncthreads();

        // barrier among the 16 jg-blocks sharing this bg
        if (tid == 0) {
            atomicAdd(&g_bar[bg], 1u);
            unsigned target = (unsigned)(t + 1) << 4;
            while (*((volatile unsigned*)&g_bar[bg]) < target) { __nanosleep(64); }
        }
        __syncthreads();
        __threadfence();
    }
}

// ---------------- MDN head ----------------
__device__ __forceinline__ void mdn_gemm(
    const float* __restrict__ At, int ldA, int mTiles, int K,
    const float* __restrict__ Bs, int ldb, float* __restrict__ Cs,
    const float* __restrict__ biasv, bool relu)
{
    for (int tile = threadIdx.x; tile < mTiles * 8; tile += blockDim.x) {
        int tm = tile % mTiles, tb = tile / mTiles;
        int m = tm << 2;
        const float* Ap = At + m;
        const float* Bp = Bs + (tb << 2);
        float acc[4][4];
#pragma unroll
        for (int i = 0; i < 4; ++i)
#pragma unroll
            for (int j = 0; j < 4; ++j) acc[i][j] = 0.f;
#pragma unroll 8
        for (int k = 0; k < K; ++k) {
            float4 a  = *reinterpret_cast<const float4*>(Ap + k * ldA);
            float4 b4 = *reinterpret_cast<const float4*>(Bp + k * ldb);
            float av[4] = {a.x, a.y, a.z, a.w};
            float bv[4] = {b4.x, b4.y, b4.z, b4.w};
#pragma unroll
            for (int i = 0; i < 4; ++i)
#pragma unroll
                for (int j = 0; j < 4; ++j) acc[i][j] = fmaf(av[i], bv[j], acc[i][j]);
        }
#pragma unroll
        for (int i = 0; i < 4; ++i) {
            float bv = biasv[m + i];
            float4 r = make_float4(acc[i][0] + bv, acc[i][1] + bv,
                                   acc[i][2] + bv, acc[i][3] + bv);
            if (relu) { r.x = fmaxf(r.x, 0.f); r.y = fmaxf(r.y, 0.f);
                        r.z = fmaxf(r.z, 0.f); r.w = fmaxf(r.w, 0.f); }
            *reinterpret_cast<float4*>(&Cs[(m + i) * 36 + (tb << 2)]) = r;
        }
    }
}

#define MDN_SMEM_BYTES ((256*32 + 112*36 + 112*36 + 176*36) * 4)

__global__ void __launch_bounds__(256, 2)
mdn_kernel(float* __restrict__ out)
{
    extern __shared__ float sm[];
    float* hT = sm;                 // [256][32]
    float* h1 = hT + 256 * 32;      // [112][36]
    float* h2 = h1 + 112 * 36;      // [112][36]
    float* o3 = h2 + 112 * 36;      // [176][36]

    const int tid = threadIdx.x;
    const int t   = blockIdx.x >> 3;
    const int bg  = blockIdx.x & 7;

    // stage h [256][32] (already k-major in g_H)
    const float* hp = g_H + (size_t)t * 65536 + (bg << 5);
    for (int i = tid; i < 2048; i += 256) {
        int k = i >> 3, nb = i & 7;
        float4 v = *reinterpret_cast<const float4*>(hp + (size_t)k * 256 + nb * 4);
        *reinterpret_cast<float4*>(&hT[k * 32 + nb * 4]) = v;
    }
    __syncthreads();

    mdn_gemm(g_W1t, 112, 28, 256, hT, 32, h1, g_b1p, true);
    __syncthreads();
    mdn_gemm(g_W2t, 112, 28, 112, h1, 36, h2, g_b2p, true);
    __syncthreads();
    mdn_gemm(g_W3t, 176, 44, 112, h2, 36, o3, g_b3p, false);
    __syncthreads();

    // epilogue: softmax(first 5), exp(next 5), copy means (160)
    if (tid < 32) {
        int n = tid;
        size_t r = (size_t)((bg << 5) + n) * NSTEP + t;
        float l[5];
        float mx = -1e30f;
#pragma unroll
        for (int k = 0; k < 5; ++k) { l[k] = o3[k * 36 + n]; mx = fmaxf(mx, l[k]); }
        float s = 0.f;
#pragma unroll
        for (int k = 0; k < 5; ++k) { l[k] = __expf(l[k] - mx); s += l[k]; }
        float inv = 1.f / s;
#pragma unroll
        for (int k = 0; k < 5; ++k) out[r * 5 + k] = l[k] * inv;
#pragma unroll
        for (int k = 0; k < 5; ++k)
            out[VARBASE + r * 5 + k] = __expf(o3[(5 + k) * 36 + n]);
    }
    for (int i = tid; i < 5120; i += 256) {
        int n = i / 160, j = i - n * 160;
        size_t r = (size_t)((bg << 5) + n) * NSTEP + t;
        out[MEANBASE + r * 160 + j] = o3[(10 + j) * 36 + n];
    }
}

extern "C" void kernel_launch(void* const* d_in, const int* in_sizes, int n_in,
                              void* d_out, int out_size)
{
    const float* x    = (const float*)d_in[0];
    const float* W_ih = (const float*)d_in[1];
    const float* W_hh = (const float*)d_in[2];
    const float* b_ih = (const float*)d_in[3];
    const float* b_hh = (const float*)d_in[4];
    const float* W1   = (const float*)d_in[5];
    const float* b1   = (const float*)d_in[6];
    const float* W2   = (const float*)d_in[7];
    const float* b2   = (const float*)d_in[8];
    const float* W3   = (const float*)d_in[9];
    const float* b3   = (const float*)d_in[10];
    float* out = (float*)d_out;

    cudaFuncSetAttribute(lstm_kernel, cudaFuncAttributeMaxDynamicSharedMemorySize, LSTM_SMEM_BYTES);
    cudaFuncSetAttribute(mdn_kernel,  cudaFuncAttributeMaxDynamicSharedMemorySize, MDN_SMEM_BYTES);

    prep_kernel<<<128, 256>>>(W1, b1, W2, b2, W3, b3);
    lstm_kernel<<<128, 128, LSTM_SMEM_BYTES>>>(x, W_ih, W_hh, b_ih, b_hh);
    mdn_kernel<<<NSTEP * 8, 256, MDN_SMEM_BYTES>>>(out);
}